// round 1
// baseline (speedup 1.0000x reference)
#include <cuda_runtime.h>
#include <math.h>

#define D_DIM 131072
#define K_SEL 5
#define TPB 512
#define MAX_B 256

// scratch for top-k indices between kernels (no allocations allowed)
__device__ int g_topk_idx[MAX_B * K_SEL];

// ---------------------------------------------------------------------------
// Kernel 1: per-row top-5 (value desc, tie-break lower index = jax stability).
// One block per row. Each thread keeps a sorted local top-5 over a strided
// float4 scan, then a shared-memory binary tree merges 5-lists.
// ---------------------------------------------------------------------------
__global__ void topk_kernel(const float* __restrict__ sims, int D) {
    const int b = blockIdx.x;
    const int t = threadIdx.x;
    const float4* row = reinterpret_cast<const float4*>(sims + (size_t)b * D);
    const int n4 = D >> 2;

    float v[K_SEL];
    int   ix[K_SEL];
#pragma unroll
    for (int j = 0; j < K_SEL; j++) { v[j] = -INFINITY; ix[j] = 0x7fffffff; }

    for (int p = t; p < n4; p += TPB) {
        float4 f = row[p];
        const int base = p << 2;
        float c[4] = {f.x, f.y, f.z, f.w};
#pragma unroll
        for (int q = 0; q < 4; q++) {
            float val = c[q];
            if (val > v[K_SEL - 1]) {      // strict >: equal value keeps earlier idx
                int id = base + q;
                int j = K_SEL - 1;
#pragma unroll
                for (; j > 0; j--) {
                    if (val > v[j - 1]) { v[j] = v[j - 1]; ix[j] = ix[j - 1]; }
                    else break;
                }
                v[j] = val; ix[j] = id;
            }
        }
    }

    __shared__ float sv[TPB * K_SEL];
    __shared__ int   si[TPB * K_SEL];
#pragma unroll
    for (int j = 0; j < K_SEL; j++) { sv[t * K_SEL + j] = v[j]; si[t * K_SEL + j] = ix[j]; }

    // tree merge of sorted 5-lists
    for (int stride = TPB >> 1; stride >= 1; stride >>= 1) {
        __syncthreads();
        if (t < stride) {
            float av[K_SEL], bv[K_SEL], mv[K_SEL];
            int   ai[K_SEL], bi[K_SEL], mi[K_SEL];
#pragma unroll
            for (int j = 0; j < K_SEL; j++) {
                av[j] = sv[t * K_SEL + j];            ai[j] = si[t * K_SEL + j];
                bv[j] = sv[(t + stride) * K_SEL + j]; bi[j] = si[(t + stride) * K_SEL + j];
            }
            int i = 0, j = 0;
#pragma unroll
            for (int m = 0; m < K_SEL; m++) {
                bool takeA = (av[i] > bv[j]) || (av[i] == bv[j] && ai[i] < bi[j]);
                if (takeA) { mv[m] = av[i]; mi[m] = ai[i]; i++; }
                else       { mv[m] = bv[j]; mi[m] = bi[j]; j++; }
            }
#pragma unroll
            for (int m = 0; m < K_SEL; m++) { sv[t * K_SEL + m] = mv[m]; si[t * K_SEL + m] = mi[m]; }
        }
    }
    __syncthreads();
    if (t < K_SEL) g_topk_idx[b * K_SEL + t] = si[t];
}

// ---------------------------------------------------------------------------
// Kernel 2: zero-fill the soft_weights region (float4 stores).
// ---------------------------------------------------------------------------
__global__ void fill_zero_kernel(float4* __restrict__ p, long long n4) {
    long long i = (long long)blockIdx.x * blockDim.x + threadIdx.x;
    long long stride = (long long)gridDim.x * blockDim.x;
    const float4 z = make_float4(0.f, 0.f, 0.f, 0.f);
    for (; i < n4; i += stride) p[i] = z;
}

// ---------------------------------------------------------------------------
// Kernel 3: scatter ones into soft_weights; write indices (value-cast float).
// ---------------------------------------------------------------------------
__global__ void scatter_kernel(float* __restrict__ out, int nBK, int idx_off, int D) {
    int t = blockIdx.x * blockDim.x + threadIdx.x;
    if (t >= nBK) return;
    int idx = g_topk_idx[t];
    out[(size_t)idx_off + (size_t)t * D + idx] = 1.0f;
    if (idx_off > 0) out[t] = (float)idx;
}

extern "C" void kernel_launch(void* const* d_in, const int* in_sizes, int n_in,
                              void* d_out, int out_size) {
    const float* sims = (const float*)d_in[0];
    const int D = D_DIM;
    int B = in_sizes[0] / D;
    if (B < 1) B = 1;
    if (B > MAX_B) B = MAX_B;

    long long soft = (long long)B * K_SEL * D;
    long long idx_off_ll = (long long)out_size - soft;
    int idx_off = (idx_off_ll > 0) ? (int)idx_off_ll : 0;

    float* outf = (float*)d_out;

    // 1) top-5 per row
    topk_kernel<<<B, TPB>>>(sims, D);

    // 2) zero soft_weights region (idx_off is a multiple of 4 floats -> 16B aligned)
    long long n4 = soft >> 2;
    int fill_blocks = (int)((n4 + 255) / 256);
    if (fill_blocks > 65535) fill_blocks = 65535;
    fill_zero_kernel<<<fill_blocks, 256>>>((float4*)(outf + idx_off), n4);

    // 3) ones + index values
    int nBK = B * K_SEL;
    scatter_kernel<<<(nBK + 127) / 128, 128>>>(outf, nBK, idx_off, D);
}

// round 2
// speedup vs baseline: 1.3113x; 1.3113x over previous
#include <cuda_runtime.h>
#include <math.h>

#define D_DIM 131072
#define K_SEL 5
#define NSEG 16
#define SEG (D_DIM / NSEG)      // 8192
#define TPB1 256
#define MAX_B 256

// inter-kernel scratch (no allocations allowed)
__device__ float g_cand_val[MAX_B * NSEG * K_SEL];
__device__ int   g_cand_idx[MAX_B * NSEG * K_SEL];
__device__ int   g_topk_idx[MAX_B * K_SEL];

// ---------------------------------------------------------------------------
// Stage 1: per-(row,segment) top-5. grid = B*NSEG blocks of 256 threads.
// Value desc, tie-break lower index (matches jax.lax.top_k stability).
// ---------------------------------------------------------------------------
__global__ void topk_stage1(const float* __restrict__ sims) {
    const int blk = blockIdx.x;
    const int b   = blk / NSEG;
    const int seg = blk % NSEG;
    const int t   = threadIdx.x;
    const int base_idx = seg * SEG;
    const float4* p = reinterpret_cast<const float4*>(
        sims + (size_t)b * D_DIM + base_idx);
    const int n4 = SEG >> 2;  // 2048

    float v[K_SEL];
    int   ix[K_SEL];
#pragma unroll
    for (int j = 0; j < K_SEL; j++) { v[j] = -INFINITY; ix[j] = 0x7fffffff; }

    // 8 strided float4 loads per thread; indices increase per thread,
    // so strict > keeps the earlier (lower) index on ties.
    for (int q4 = t; q4 < n4; q4 += TPB1) {
        float4 f = p[q4];
        const int bi = base_idx + (q4 << 2);
        float c[4] = {f.x, f.y, f.z, f.w};
#pragma unroll
        for (int q = 0; q < 4; q++) {
            float val = c[q];
            if (val > v[K_SEL - 1]) {
                int id = bi + q;
                int j = K_SEL - 1;
#pragma unroll
                for (; j > 0; j--) {
                    if (val > v[j - 1]) { v[j] = v[j - 1]; ix[j] = ix[j - 1]; }
                    else break;
                }
                v[j] = val; ix[j] = id;
            }
        }
    }

    __shared__ float sv[TPB1 * K_SEL];
    __shared__ int   si[TPB1 * K_SEL];
#pragma unroll
    for (int j = 0; j < K_SEL; j++) { sv[t * K_SEL + j] = v[j]; si[t * K_SEL + j] = ix[j]; }

    for (int stride = TPB1 >> 1; stride >= 1; stride >>= 1) {
        __syncthreads();
        if (t < stride) {
            float av[K_SEL], bv[K_SEL], mv[K_SEL];
            int   ai[K_SEL], bi2[K_SEL], mi[K_SEL];
#pragma unroll
            for (int j = 0; j < K_SEL; j++) {
                av[j]  = sv[t * K_SEL + j];            ai[j]  = si[t * K_SEL + j];
                bv[j]  = sv[(t + stride) * K_SEL + j]; bi2[j] = si[(t + stride) * K_SEL + j];
            }
            int i = 0, j = 0;
#pragma unroll
            for (int m = 0; m < K_SEL; m++) {
                bool takeA = (av[i] > bv[j]) || (av[i] == bv[j] && ai[i] < bi2[j]);
                if (takeA) { mv[m] = av[i]; mi[m] = ai[i]; i++; }
                else       { mv[m] = bv[j]; mi[m] = bi2[j]; j++; }
            }
#pragma unroll
            for (int m = 0; m < K_SEL; m++) { sv[t * K_SEL + m] = mv[m]; si[t * K_SEL + m] = mi[m]; }
        }
    }
    __syncthreads();
    if (t < K_SEL) {
        g_cand_val[(b * NSEG + seg) * K_SEL + t] = sv[t];
        g_cand_idx[(b * NSEG + seg) * K_SEL + t] = si[t];
    }
}

// ---------------------------------------------------------------------------
// Stage 2: one thread per row merges NSEG*K candidates -> final top-5.
// Candidates scanned in increasing-index order, strict > keeps earlier idx.
// ---------------------------------------------------------------------------
__global__ void topk_stage2(int B) {
    int b = blockIdx.x * blockDim.x + threadIdx.x;
    if (b >= B) return;
    float v[K_SEL];
    int   ix[K_SEL];
#pragma unroll
    for (int j = 0; j < K_SEL; j++) { v[j] = -INFINITY; ix[j] = 0x7fffffff; }
    const float* cv = &g_cand_val[b * NSEG * K_SEL];
    const int*   ci = &g_cand_idx[b * NSEG * K_SEL];
    for (int n = 0; n < NSEG * K_SEL; n++) {
        float val = cv[n];
        if (val > v[K_SEL - 1]) {
            int id = ci[n];
            int j = K_SEL - 1;
#pragma unroll
            for (; j > 0; j--) {
                if (val > v[j - 1]) { v[j] = v[j - 1]; ix[j] = ix[j - 1]; }
                else break;
            }
            v[j] = val; ix[j] = id;
        }
    }
#pragma unroll
    for (int j = 0; j < K_SEL; j++) g_topk_idx[b * K_SEL + j] = ix[j];
}

// ---------------------------------------------------------------------------
// Persistent zero-fill: few fat CTAs, long grid-stride store streams.
// ---------------------------------------------------------------------------
__global__ void fill_zero_kernel(float4* __restrict__ p, long long n4) {
    long long i = (long long)blockIdx.x * blockDim.x + threadIdx.x;
    const long long stride = (long long)gridDim.x * blockDim.x;
    const float4 z = make_float4(0.f, 0.f, 0.f, 0.f);
    for (; i < n4; i += stride) p[i] = z;
}

// ---------------------------------------------------------------------------
// Scatter ones + hard indices (value-cast to float in the front region).
// ---------------------------------------------------------------------------
__global__ void scatter_kernel(float* __restrict__ out, int nBK, int idx_off) {
    int t = blockIdx.x * blockDim.x + threadIdx.x;
    if (t >= nBK) return;
    int idx = g_topk_idx[t];
    out[(size_t)idx_off + (size_t)t * D_DIM + idx] = 1.0f;
    if (idx_off > 0) out[t] = (float)idx;
}

extern "C" void kernel_launch(void* const* d_in, const int* in_sizes, int n_in,
                              void* d_out, int out_size) {
    const float* sims = (const float*)d_in[0];
    int B = in_sizes[0] / D_DIM;
    if (B < 1) B = 1;
    if (B > MAX_B) B = MAX_B;

    long long soft = (long long)B * K_SEL * D_DIM;
    long long idx_off_ll = (long long)out_size - soft;
    int idx_off = (idx_off_ll > 0) ? (int)idx_off_ll : 0;

    float* outf = (float*)d_out;

    // 1) per-segment top-5 (B*NSEG blocks — full chip)
    topk_stage1<<<B * NSEG, TPB1>>>(sims);

    // 2) merge candidates per row
    topk_stage2<<<(B + 63) / 64, 64>>>(B);

    // 3) zero soft_weights (persistent store stream)
    long long n4 = soft >> 2;
    fill_zero_kernel<<<1184, 256>>>((float4*)(outf + idx_off), n4);

    // 4) ones + index values
    int nBK = B * K_SEL;
    scatter_kernel<<<(nBK + 127) / 128, 128>>>(outf, nBK, idx_off);
}

// round 3
// speedup vs baseline: 1.4314x; 1.0916x over previous
#include <cuda_runtime.h>
#include <math.h>

#define D_DIM 131072
#define K_SEL 5
#define NSEG 16
#define SEG (D_DIM / NSEG)      // 8192
#define TPB1 256
#define MAX_B 256
#define CHUNK_FLOATS 32768      // 128KB per fill CTA (divides D_DIM exactly)

// inter-kernel scratch (no allocations allowed)
__device__ float g_cand_val[MAX_B * NSEG * K_SEL];
__device__ int   g_cand_idx[MAX_B * NSEG * K_SEL];

// ---------------------------------------------------------------------------
// Stage 1: per-(row,segment) top-5. grid = B*NSEG blocks of 256 threads.
// Value desc, tie-break lower index (matches jax.lax.top_k stability).
// ---------------------------------------------------------------------------
__global__ void topk_stage1(const float* __restrict__ sims) {
    const int blk = blockIdx.x;
    const int b   = blk / NSEG;
    const int seg = blk % NSEG;
    const int t   = threadIdx.x;
    const int base_idx = seg * SEG;
    const float4* p = reinterpret_cast<const float4*>(
        sims + (size_t)b * D_DIM + base_idx);
    const int n4 = SEG >> 2;  // 2048

    float v[K_SEL];
    int   ix[K_SEL];
#pragma unroll
    for (int j = 0; j < K_SEL; j++) { v[j] = -INFINITY; ix[j] = 0x7fffffff; }

    for (int q4 = t; q4 < n4; q4 += TPB1) {
        float4 f = p[q4];
        const int bi = base_idx + (q4 << 2);
        float c[4] = {f.x, f.y, f.z, f.w};
#pragma unroll
        for (int q = 0; q < 4; q++) {
            float val = c[q];
            if (val > v[K_SEL - 1]) {
                int id = bi + q;
                int j = K_SEL - 1;
#pragma unroll
                for (; j > 0; j--) {
                    if (val > v[j - 1]) { v[j] = v[j - 1]; ix[j] = ix[j - 1]; }
                    else break;
                }
                v[j] = val; ix[j] = id;
            }
        }
    }

    __shared__ float sv[TPB1 * K_SEL];
    __shared__ int   si[TPB1 * K_SEL];
#pragma unroll
    for (int j = 0; j < K_SEL; j++) { sv[t * K_SEL + j] = v[j]; si[t * K_SEL + j] = ix[j]; }

    for (int stride = TPB1 >> 1; stride >= 1; stride >>= 1) {
        __syncthreads();
        if (t < stride) {
            float av[K_SEL], bv[K_SEL], mv[K_SEL];
            int   ai[K_SEL], bi2[K_SEL], mi[K_SEL];
#pragma unroll
            for (int j = 0; j < K_SEL; j++) {
                av[j]  = sv[t * K_SEL + j];            ai[j]  = si[t * K_SEL + j];
                bv[j]  = sv[(t + stride) * K_SEL + j]; bi2[j] = si[(t + stride) * K_SEL + j];
            }
            int i = 0, j = 0;
#pragma unroll
            for (int m = 0; m < K_SEL; m++) {
                bool takeA = (av[i] > bv[j]) || (av[i] == bv[j] && ai[i] < bi2[j]);
                if (takeA) { mv[m] = av[i]; mi[m] = ai[i]; i++; }
                else       { mv[m] = bv[j]; mi[m] = bi2[j]; j++; }
            }
#pragma unroll
            for (int m = 0; m < K_SEL; m++) { sv[t * K_SEL + m] = mv[m]; si[t * K_SEL + m] = mi[m]; }
        }
    }
    __syncthreads();
    if (t < K_SEL) {
        g_cand_val[(b * NSEG + seg) * K_SEL + t] = sv[t];
        g_cand_idx[(b * NSEG + seg) * K_SEL + t] = si[t];
    }
}

// ---------------------------------------------------------------------------
// Merge NSEG*K candidates of one row -> top-5 indices (sorted desc by value,
// tie-break lower index). Scans candidates in increasing-index order so
// strict > keeps the earlier index on ties.
// ---------------------------------------------------------------------------
__device__ __forceinline__ void merge_row(int b, int* ix_out) {
    float v[K_SEL];
    int   ix[K_SEL];
#pragma unroll
    for (int j = 0; j < K_SEL; j++) { v[j] = -INFINITY; ix[j] = 0x7fffffff; }
    const float* cv = &g_cand_val[b * NSEG * K_SEL];
    const int*   ci = &g_cand_idx[b * NSEG * K_SEL];
    for (int n = 0; n < NSEG * K_SEL; n++) {
        float val = cv[n];
        if (val > v[K_SEL - 1]) {
            int id = ci[n];
            int j = K_SEL - 1;
#pragma unroll
            for (; j > 0; j--) {
                if (val > v[j - 1]) { v[j] = v[j - 1]; ix[j] = ix[j - 1]; }
                else break;
            }
            v[j] = val; ix[j] = id;
        }
    }
#pragma unroll
    for (int j = 0; j < K_SEL; j++) ix_out[j] = ix[j];
}

// ---------------------------------------------------------------------------
// Fused fill + scatter. One CTA per 128KB chunk of the soft_weights region.
// TMA bulk stores (bypass the 12-cyc STG.128 issue floor), then one-hot
// overwrite + index front-region write.
// ---------------------------------------------------------------------------
__global__ void fill_scatter_kernel(float* __restrict__ out, int idx_off, int B) {
    __shared__ float4 zbuf[1024];   // 16KB of zeros
    const int t = threadIdx.x;      // 256 threads

    const float4 z = make_float4(0.f, 0.f, 0.f, 0.f);
#pragma unroll
    for (int i = t; i < 1024; i += 256) zbuf[i] = z;
    __syncthreads();
    asm volatile("fence.proxy.async.shared::cta;" ::: "memory");

    const long long start = (long long)blockIdx.x * CHUNK_FLOATS;  // soft-region offset
    float* dst = out + idx_off + start;

    if (t == 0) {
        unsigned saddr = (unsigned)__cvta_generic_to_shared(zbuf);
        const int sz = 16384;
#pragma unroll
        for (int c = 0; c < 8; c++) {
            asm volatile(
                "cp.async.bulk.global.shared::cta.bulk_group [%0], [%1], %2;"
                :: "l"(dst + c * 4096), "r"(saddr), "r"(sz) : "memory");
        }
        asm volatile("cp.async.bulk.commit_group;" ::: "memory");
    }

    // front region: hard indices as float (block 0, one thread per row)
    if (blockIdx.x == 0 && idx_off > 0 && t >= 32 && t < 32 + B) {
        int b = t - 32;
        int ix[K_SEL];
        merge_row(b, ix);
#pragma unroll
        for (int j = 0; j < K_SEL; j++) out[b * K_SEL + j] = (float)ix[j];
    }

    if (t == 0) {
        // which (b,k) plane does this chunk live in?
        long long bk = start / D_DIM;
        int b = (int)(bk / K_SEL);
        int k = (int)(bk % K_SEL);
        long long plane_off = start - bk * (long long)D_DIM;

        int ix[K_SEL];
        merge_row(b, ix);
        int sel = ix[k];

        // wait for this CTA's bulk stores, then overwrite the one-hot slot
        asm volatile("cp.async.bulk.wait_group 0;" ::: "memory");
        if (sel >= plane_off && sel < plane_off + CHUNK_FLOATS) {
            dst[sel - plane_off] = 1.0f;
        }
    }
}

extern "C" void kernel_launch(void* const* d_in, const int* in_sizes, int n_in,
                              void* d_out, int out_size) {
    const float* sims = (const float*)d_in[0];
    int B = in_sizes[0] / D_DIM;
    if (B < 1) B = 1;
    if (B > MAX_B) B = MAX_B;

    long long soft = (long long)B * K_SEL * D_DIM;
    long long idx_off_ll = (long long)out_size - soft;
    int idx_off = (idx_off_ll > 0) ? (int)idx_off_ll : 0;

    float* outf = (float*)d_out;

    // 1) per-segment top-5 candidates
    topk_stage1<<<B * NSEG, TPB1>>>(sims);

    // 2) fused zero-fill (TMA bulk stores) + one-hot scatter + index write
    int nchunks = (int)(soft / CHUNK_FLOATS);   // 1280 for B=64
    fill_scatter_kernel<<<nchunks, 256>>>(outf, idx_off, B);
}

// round 4
// speedup vs baseline: 1.8005x; 1.2578x over previous
#include <cuda_runtime.h>
#include <math.h>

#define D_DIM 131072
#define K_SEL 5
#define NSEG 16
#define SEG (D_DIM / NSEG)      // 8192
#define TPB1 256
#define MAX_B 256
#define CHUNK_FLOATS 32768      // 128KB per fill CTA (divides D_DIM exactly)
#define NCAND (NSEG * K_SEL)    // 80 candidates per row

// inter-kernel scratch (no allocations allowed)
__device__ float g_cand_val[MAX_B * NCAND];
__device__ int   g_cand_idx[MAX_B * NCAND];
__device__ int   g_topk_idx[MAX_B * K_SEL];

// ---------------------------------------------------------------------------
// Stage 1: per-(row,segment) top-5. grid = B*NSEG blocks of 256 threads.
// All 8 float4 loads issued back-to-back (MLP=8) BEFORE the data-dependent
// insertion sort, so the warp is never stuck at MLP=1.
// ---------------------------------------------------------------------------
__global__ void topk_stage1(const float* __restrict__ sims) {
    const int blk = blockIdx.x;
    const int b   = blk / NSEG;
    const int seg = blk % NSEG;
    const int t   = threadIdx.x;
    const int base_idx = seg * SEG;
    const float4* p = reinterpret_cast<const float4*>(
        sims + (size_t)b * D_DIM + base_idx);

    // ---- load phase: 8 independent LDG.128 ----
    float4 r[8];
#pragma unroll
    for (int i = 0; i < 8; i++) r[i] = p[t + i * TPB1];

    // ---- select phase: per-thread sorted top-5 ----
    float v[K_SEL];
    int   ix[K_SEL];
#pragma unroll
    for (int j = 0; j < K_SEL; j++) { v[j] = -INFINITY; ix[j] = 0x7fffffff; }

#pragma unroll
    for (int i = 0; i < 8; i++) {
        const int bi = base_idx + ((t + i * TPB1) << 2);
        float c[4] = {r[i].x, r[i].y, r[i].z, r[i].w};
#pragma unroll
        for (int q = 0; q < 4; q++) {
            float val = c[q];
            if (val > v[K_SEL - 1]) {     // strict >: earlier index wins ties
                int id = bi + q;
                int j = K_SEL - 1;
#pragma unroll
                for (; j > 0; j--) {
                    if (val > v[j - 1]) { v[j] = v[j - 1]; ix[j] = ix[j - 1]; }
                    else break;
                }
                v[j] = val; ix[j] = id;
            }
        }
    }

    // ---- smem tree merge of sorted 5-lists ----
    __shared__ float sv[TPB1 * K_SEL];
    __shared__ int   si[TPB1 * K_SEL];
#pragma unroll
    for (int j = 0; j < K_SEL; j++) { sv[t * K_SEL + j] = v[j]; si[t * K_SEL + j] = ix[j]; }

    for (int stride = TPB1 >> 1; stride >= 1; stride >>= 1) {
        __syncthreads();
        if (t < stride) {
            float av[K_SEL], bv[K_SEL], mv[K_SEL];
            int   ai[K_SEL], bi2[K_SEL], mi[K_SEL];
#pragma unroll
            for (int j = 0; j < K_SEL; j++) {
                av[j]  = sv[t * K_SEL + j];            ai[j]  = si[t * K_SEL + j];
                bv[j]  = sv[(t + stride) * K_SEL + j]; bi2[j] = si[(t + stride) * K_SEL + j];
            }
            int i = 0, j = 0;
#pragma unroll
            for (int m = 0; m < K_SEL; m++) {
                bool takeA = (av[i] > bv[j]) || (av[i] == bv[j] && ai[i] < bi2[j]);
                if (takeA) { mv[m] = av[i]; mi[m] = ai[i]; i++; }
                else       { mv[m] = bv[j]; mi[m] = bi2[j]; j++; }
            }
#pragma unroll
            for (int m = 0; m < K_SEL; m++) { sv[t * K_SEL + m] = mv[m]; si[t * K_SEL + m] = mi[m]; }
        }
    }
    __syncthreads();
    if (t < K_SEL) {
        g_cand_val[(b * NSEG + seg) * K_SEL + t] = sv[t];
        g_cand_idx[(b * NSEG + seg) * K_SEL + t] = si[t];
    }
}

// ---------------------------------------------------------------------------
// Stage 2: one WARP per row. Lanes cooperatively hold the 80 candidates
// (up to 3 each, loaded with full MLP), then 5 rounds of warp argmax
// (val desc, idx asc tie-break). Writes g_topk_idx and the float-cast
// index front region of the output.
// ---------------------------------------------------------------------------
__global__ void topk_stage2(float* __restrict__ out, int idx_off, int B) {
    const int warp = (blockIdx.x * blockDim.x + threadIdx.x) >> 5;
    const int lane = threadIdx.x & 31;
    if (warp >= B) return;
    const int b = warp;

    // lane l owns candidates l, l+32, l+64 (third only for l < 16)
    float cv[3]; int ci[3];
#pragma unroll
    for (int s = 0; s < 3; s++) {
        int n = lane + s * 32;
        if (n < NCAND) {
            cv[s] = g_cand_val[b * NCAND + n];
            ci[s] = g_cand_idx[b * NCAND + n];
        } else { cv[s] = -INFINITY; ci[s] = 0x7fffffff; }
    }

#pragma unroll
    for (int r = 0; r < K_SEL; r++) {
        // local best among this lane's live candidates
        float bestv = cv[0]; int besti = ci[0];
#pragma unroll
        for (int s = 1; s < 3; s++) {
            bool better = (cv[s] > bestv) || (cv[s] == bestv && ci[s] < besti);
            if (better) { bestv = cv[s]; besti = ci[s]; }
        }
        // warp argmax reduce
#pragma unroll
        for (int off = 16; off >= 1; off >>= 1) {
            float ov = __shfl_down_sync(0xffffffff, bestv, off);
            int   oi = __shfl_down_sync(0xffffffff, besti, off);
            bool better = (ov > bestv) || (ov == bestv && oi < besti);
            if (better) { bestv = ov; besti = oi; }
        }
        // broadcast winner
        bestv = __shfl_sync(0xffffffff, bestv, 0);
        besti = __shfl_sync(0xffffffff, besti, 0);
        if (lane == 0) {
            g_topk_idx[b * K_SEL + r] = besti;
            if (idx_off > 0) out[b * K_SEL + r] = (float)besti;
        }
        // consume the winner
#pragma unroll
        for (int s = 0; s < 3; s++)
            if (ci[s] == besti) { cv[s] = -INFINITY; ci[s] = 0x7fffffff; }
    }
}

// ---------------------------------------------------------------------------
// Fill + scatter. One CTA per 128KB chunk; threads 0..7 each issue one 16KB
// TMA bulk store (per-thread bulk_group), wait, and the owning thread
// patches the one-hot element.
// ---------------------------------------------------------------------------
__global__ void fill_scatter_kernel(float* __restrict__ out, int idx_off) {
    __shared__ float4 zbuf[1024];   // 16KB of zeros
    const int t = threadIdx.x;      // 256 threads

    const float4 z = make_float4(0.f, 0.f, 0.f, 0.f);
#pragma unroll
    for (int i = t; i < 1024; i += 256) zbuf[i] = z;
    __syncthreads();
    asm volatile("fence.proxy.async.shared::cta;" ::: "memory");

    const long long start = (long long)blockIdx.x * CHUNK_FLOATS;
    float* dst = out + idx_off + start;

    if (t < 8) {
        unsigned saddr = (unsigned)__cvta_generic_to_shared(zbuf);
        asm volatile(
            "cp.async.bulk.global.shared::cta.bulk_group [%0], [%1], %2;"
            :: "l"(dst + t * 4096), "r"(saddr), "r"(16384) : "memory");
        asm volatile("cp.async.bulk.commit_group;" ::: "memory");

        // this chunk lies in exactly one (b,k) plane
        long long bk = start / D_DIM;
        long long plane_off = start - bk * (long long)D_DIM;
        int sel = g_topk_idx[bk];                 // final index for this plane
        long long rel = (long long)sel - plane_off - (long long)t * 4096;

        asm volatile("cp.async.bulk.wait_group 0;" ::: "memory");
        if (rel >= 0 && rel < 4096) dst[t * 4096 + rel] = 1.0f;
    }
}

extern "C" void kernel_launch(void* const* d_in, const int* in_sizes, int n_in,
                              void* d_out, int out_size) {
    const float* sims = (const float*)d_in[0];
    int B = in_sizes[0] / D_DIM;
    if (B < 1) B = 1;
    if (B > MAX_B) B = MAX_B;

    long long soft = (long long)B * K_SEL * D_DIM;
    long long idx_off_ll = (long long)out_size - soft;
    int idx_off = (idx_off_ll > 0) ? (int)idx_off_ll : 0;

    float* outf = (float*)d_out;

    // 1) per-segment top-5 candidates (MLP-8 loads)
    topk_stage1<<<B * NSEG, TPB1>>>(sims);

    // 2) warp-per-row final merge + index front region
    topk_stage2<<<(B + 3) / 4, 128>>>(outf, idx_off, B);

    // 3) zero-fill via parallel TMA bulk stores + one-hot patch
    int nchunks = (int)(soft / CHUNK_FLOATS);   // 1280 for B=64
    fill_scatter_kernel<<<nchunks, 256>>>(outf, idx_off);
}

// round 5
// speedup vs baseline: 3.4526x; 1.9176x over previous
#include <cuda_runtime.h>
#include <math.h>

#define D_DIM 131072
#define K_SEL 5
#define WARPS_PER_ROW 128          // 1024 elems per warp
#define TPB1 256
#define MAX_B 128
#define NCAND (WARPS_PER_ROW * K_SEL)   // 640 candidates per row

// inter-kernel scratch (no allocations allowed)
__device__ unsigned long long g_cand[MAX_B * NCAND];

// monotonic float->uint transform (order-preserving incl. negatives)
__device__ __forceinline__ unsigned ford(float f) {
    unsigned u = __float_as_uint(f);
    return u ^ (((int)u >> 31) | 0x80000000u);
}

// ---------------------------------------------------------------------------
// Stage 1: warp-per-1024-elements top-5. No smem, no syncthreads, no
// dynamic array indexing. Per-thread branchless argmax, 5 warp-argmax
// rounds, winner-lane register rescan with dead-bit mask.
// ---------------------------------------------------------------------------
__global__ void topk_stage1(const float* __restrict__ sims) {
    const int gw   = (blockIdx.x * TPB1 + threadIdx.x) >> 5;
    const int lane = threadIdx.x & 31;
    const int b    = gw / WARPS_PER_ROW;
    const int w    = gw % WARPS_PER_ROW;
    const int base = w * 1024;
    const float4* p = reinterpret_cast<const float4*>(
        sims + (size_t)b * D_DIM + base);

    // 8 back-to-back LDG.128 (MLP=8)
    float4 r[8];
#pragma unroll
    for (int i = 0; i < 8; i++) r[i] = p[lane + i * 32];

    float c[32];
#pragma unroll
    for (int i = 0; i < 8; i++) {
        c[4*i+0] = r[i].x; c[4*i+1] = r[i].y;
        c[4*i+2] = r[i].z; c[4*i+3] = r[i].w;
    }

    // per-thread argmax; ids increase with e, strict > keeps lowest idx
    float bv = -INFINITY; int bi = 0x7fffffff; int be = 0;
#pragma unroll
    for (int i = 0; i < 8; i++)
#pragma unroll
        for (int q = 0; q < 4; q++) {
            const int e = 4*i + q;
            if (c[e] > bv) {
                bv = c[e]; bi = base + ((lane + i*32) << 2) + q; be = e;
            }
        }

    unsigned dead = 0u;
#pragma unroll
    for (int rr = 0; rr < K_SEL; rr++) {
        // warp argmax (val desc, idx asc)
        float wv = bv; int wi = bi;
#pragma unroll
        for (int off = 16; off >= 1; off >>= 1) {
            float ov = __shfl_down_sync(0xffffffffu, wv, off);
            int   oi = __shfl_down_sync(0xffffffffu, wi, off);
            if (ov > wv || (ov == wv && oi < wi)) { wv = ov; wi = oi; }
        }
        wv = __shfl_sync(0xffffffffu, wv, 0);
        wi = __shfl_sync(0xffffffffu, wi, 0);

        if (lane == rr)
            g_cand[(b * WARPS_PER_ROW + w) * K_SEL + rr] =
                ((unsigned long long)ford(wv) << 32) | (unsigned)(~wi);

        // exactly one lane owns wi: kill it and rescan its registers
        if (bi == wi) {
            dead |= (1u << be);
            bv = -INFINITY; bi = 0x7fffffff; be = 0;
#pragma unroll
            for (int i = 0; i < 8; i++)
#pragma unroll
                for (int q = 0; q < 4; q++) {
                    const int e = 4*i + q;
                    float val = ((dead >> e) & 1u) ? -INFINITY : c[e];
                    if (val > bv) {
                        bv = val; bi = base + ((lane + i*32) << 2) + q; be = e;
                    }
                }
        }
    }
}

// ---------------------------------------------------------------------------
// Stage 2: warp-per-row merge of 640 packed candidates -> write float-cast
// indices (front region) + one-hot 1.0f patches (after the memset).
// Packed u64 compare = value desc with idx-asc tie-break.
// ---------------------------------------------------------------------------
__global__ void topk_stage2(float* __restrict__ out, int idx_off, int B) {
    const int warp = (blockIdx.x * blockDim.x + threadIdx.x) >> 5;
    const int lane = threadIdx.x & 31;
    if (warp >= B) return;
    const int b = warp;

    unsigned long long k[20];
#pragma unroll
    for (int s = 0; s < 20; s++)
        k[s] = g_cand[b * NCAND + lane + s * 32];

    unsigned dead = 0u;
#pragma unroll
    for (int rr = 0; rr < K_SEL; rr++) {
        unsigned long long bk = 0ull; int bs = 0;
#pragma unroll
        for (int s = 0; s < 20; s++) {
            bool live = !((dead >> s) & 1u);
            if (live && k[s] > bk) { bk = k[s]; bs = s; }
        }
        unsigned long long wk = bk;
#pragma unroll
        for (int off = 16; off >= 1; off >>= 1) {
            unsigned long long ok = __shfl_down_sync(0xffffffffu, wk, off);
            if (ok > wk) wk = ok;
        }
        wk = __shfl_sync(0xffffffffu, wk, 0);
        if (bk == wk) dead |= (1u << bs);     // keys unique -> one winner lane

        if (lane == 0) {
            int idx = (int)(~(unsigned)wk);
            if (idx_off > 0) out[b * K_SEL + rr] = (float)idx;
            out[(size_t)idx_off + ((size_t)b * K_SEL + rr) * D_DIM + idx] = 1.0f;
        }
    }
}

extern "C" void kernel_launch(void* const* d_in, const int* in_sizes, int n_in,
                              void* d_out, int out_size) {
    const float* sims = (const float*)d_in[0];
    int B = in_sizes[0] / D_DIM;
    if (B < 1) B = 1;
    if (B > MAX_B) B = MAX_B;

    long long soft = (long long)B * K_SEL * D_DIM;
    long long idx_off_ll = (long long)out_size - soft;
    int idx_off = (idx_off_ll > 0) ? (int)idx_off_ll : 0;

    float* outf = (float*)d_out;

    // 1) vendor-tuned zero fill of the whole output (memset graph node)
    cudaMemsetAsync(d_out, 0, (size_t)out_size * sizeof(float), 0);

    // 2) per-warp-segment top-5 candidates
    topk_stage1<<<B * WARPS_PER_ROW * 32 / TPB1, TPB1>>>(sims);

    // 3) final merge + index front region + one-hot patches
    topk_stage2<<<(B * 32 + 255) / 256, 256>>>(outf, idx_off, B);
}